// round 7
// baseline (speedup 1.0000x reference)
#include <cuda_runtime.h>
#include <math.h>

#define NW   14
#define QDIM 16384
#define QBATCH 1024
#define NT   1024
#define NSM  148

typedef unsigned long long ull;

// ================= compile-time GF(2) circuit algebra =================
__host__ __device__ constexpr unsigned sig(unsigned y) { return y ^ (y >> 7); }

struct PassC {
    unsigned combo[16];   // sigma-transformed XOR offsets (psi addressing)
    unsigned craw[16];    // raw XOR offsets (stage addressing, pass 0)
    unsigned rmask[4];    // parity masks on logical rep yr
    int      gate[4];
    int      zflip[4];    // 1 if flip provably always 0
    int      K;
    int      ngrp;
    unsigned gmask[12];
    int      gshift[12];
};

__host__ __device__ constexpr unsigned hc(unsigned x, int c, int t) {
    int pc = 13 - c, pt = 13 - t;
    return x ^ (((x >> pc) & 1u) << pt);
}
__host__ __device__ constexpr unsigned Gf(unsigned x) {
    x = hc(x, 13, 0);
    for (int w = 12; w >= 0; --w) x = hc(x, w, w + 1);
    return x;
}
__host__ __device__ constexpr unsigned Gi(unsigned x) {
    for (int w = 0; w <= 12; ++w) x = hc(x, w, w + 1);
    x = hc(x, 13, 0);
    return x;
}
__host__ __device__ constexpr unsigned colV(int L, int w) {
    unsigned e = 1u << (13 - w);
    for (int i = 0; i < L; i++) e = Gf(e);
    return e;
}
__host__ __device__ constexpr unsigned rowR(int L, int w) {
    unsigned rr = 0;
    for (int j = 0; j < 14; j++) {
        unsigned e = 1u << j;
        for (int i = 0; i < L; i++) e = Gi(e);
        rr |= ((e >> (13 - w)) & 1u) << j;
    }
    return rr;
}

__host__ __device__ constexpr PassC build_pass(int pi) {
    PassC P = {};
    const int L = pi / 4, g = pi % 4;
    const int gstart[4] = {0, 4, 8, 11};
    const int gcnt[4]   = {4, 4, 3, 3};
    const int K = gcnt[g], base = gstart[g];

    unsigned vs[4] = {}, rs[4] = {};
    for (int j = 0; j < K; j++) {
        vs[j] = colV(L, base + j);
        rs[j] = rowR(L, base + j);
    }
    for (int kk = 0; kk < 16; kk++) {
        unsigned cb = 0;
        if (kk < (1 << K))
            for (int j = 0; j < K; j++)
                if ((kk >> j) & 1) cb ^= vs[j];
        P.craw[kk]  = cb;
        P.combo[kk] = sig(cb);
    }
    // Gaussian elimination, high-bit pivots
    bool ispiv[14] = {};
    unsigned red[4] = {}; int piv[4] = {};
    for (int j = 0; j < K; j++) {
        unsigned u = vs[j];
        for (int q = 0; q < j; q++)
            if ((u >> piv[q]) & 1u) u ^= red[q];
        int hb = 13;
        while (hb > 0 && !((u >> hb) & 1u)) hb--;
        piv[j] = hb; red[j] = u; ispiv[hb] = true;
    }
    const int NF = 14 - K;
    bool used[14] = {};
    for (int b = 0; b < 14; b++) used[b] = ispiv[b];

    // lane-bit placement: lane bit t -> position t or t+7 (bank-conflict-free sigma)
    int Pm[14] = {};
    for (int t = 0; t < 4; t++) {
        int pos = -1;
        if (!used[t]) pos = t;
        else if (!used[t + 7]) pos = t + 7;
        if (pos >= 0) { used[pos] = true; Pm[t] = pos; }
        else Pm[t] = -1;
    }
    for (int t = 0; t < 4; t++) {
        if (Pm[t] < 0) {
            for (int b = 0; b < 14; b++)
                if (!used[b]) { Pm[t] = b; used[b] = true; break; }
        }
    }
    int idx = 4;
    for (int b = 0; b < 14; b++)
        if (!used[b]) { Pm[idx++] = b; used[b] = true; }

    unsigned freemask = 0;
    for (int i = 0; i < NF; i++) freemask |= 1u << Pm[i];

    for (int j = 0; j < 4; j++) {
        P.rmask[j] = (j < K) ? rs[j] : 0u;
        P.gate[j]  = (j < K) ? (L * 14 + base + j) : 0;
        P.zflip[j] = (j < K) ? (((rs[j] & freemask) == 0u) ? 1 : 0) : 1;
    }

    // run-compress (o bit i -> position Pm[i]) into (mask, shift) groups
    P.K = K; P.ngrp = 0;
    int i = 0;
    while (i < NF) {
        int d = Pm[i] - i;
        unsigned m = 0; int j2 = i;
        while (j2 < NF && Pm[j2] - j2 == d) { m |= 1u << j2; j2++; }
        P.gmask[P.ngrp]  = m;
        P.gshift[P.ngrp] = d;
        P.ngrp++;
        i = j2;
    }
    return P;
}

// ================= packed f32x2 helpers =================
__device__ __forceinline__ ull pk2(float lo, float hi) {
    ull r;
    asm("mov.b64 %0, {%1, %2};" : "=l"(r) : "f"(lo), "f"(hi));
    return r;
}
__device__ __forceinline__ ull swp(ull v) {
    unsigned lo, hi;
    asm("mov.b64 {%0, %1}, %2;" : "=r"(lo), "=r"(hi) : "l"(v));
    ull r;
    asm("mov.b64 %0, {%1, %2};" : "=l"(r) : "r"(hi), "r"(lo));
    return r;
}
__device__ __forceinline__ ull f2(ull a, ull b, ull c) {
    ull d;
    asm("fma.rn.f32x2 %0, %1, %2, %3;" : "=l"(d) : "l"(a), "l"(b), "l"(c));
    return d;
}
__device__ __forceinline__ ull m2(ull a, ull b) {
    ull d;
    asm("mul.rn.f32x2 %0, %1, %2;" : "=l"(d) : "l"(a), "l"(b));
    return d;
}

// ================= cp.async prefetch =================
__device__ __forceinline__ void prefetch_state(float* stage, const float* g, int tid)
{
    #pragma unroll
    for (int i = 0; i < QDIM / (4 * NT); i++) {        // 4 chunks of 16B
        const int c = tid + i * NT;
        const unsigned sa = (unsigned)__cvta_generic_to_shared(stage + c * 4);
        asm volatile("cp.async.cg.shared.global [%0], [%1], 16;"
                     :: "r"(sa), "l"(g + c * 4));
    }
    asm volatile("cp.async.commit_group;" ::: "memory");
}

// ================= fused-gate pass =================
template<int PI, bool FIRST>
__device__ __forceinline__ void do_pass(ull* psiu, const float* stage,
                                        const ulonglong2* pkv, int tid)
{
    constexpr PassC P  = build_pass(PI);
    constexpr int K    = P.K;
    constexpr int NE   = 1 << K;
    constexpr int NORB = 1 << (NW - K);

    #pragma unroll
    for (int o = tid; o < NORB; o += NT) {
        unsigned yr = 0;
        #pragma unroll
        for (int g = 0; g < P.ngrp; g++)
            yr |= ((unsigned)o & P.gmask[g]) << P.gshift[g];
        const unsigned syr = sig(yr);

        ull e[NE];
        if (FIRST) {
            #pragma unroll
            for (int kk = 0; kk < NE; kk++)
                e[kk] = pk2(stage[yr ^ P.craw[kk]], 0.0f);
        } else {
            #pragma unroll
            for (int kk = 0; kk < NE; kk++)
                e[kk] = psiu[syr ^ P.combo[kk]];
        }

        #pragma unroll
        for (int j = 0; j < K; j++) {
            const int flip = P.zflip[j] ? 0 : (__popc(yr & P.rmask[j]) & 1);
            const ulonglong2* cp = pkv + (size_t)((P.gate[j] << 1) + flip) * 3;
            const ulonglong2 c0 = cp[0], c1 = cp[1], c2 = cp[2];
            const ull A = c0.x, Ai = c0.y, Ain = c1.x;
            const ull B = c1.y, Bn = c2.x, Bi  = c2.y;
            #pragma unroll
            for (int kk = 0; kk < NE; kk++) {
                if (!((kk >> j) & 1)) {
                    const int k1 = kk | (1 << j);
                    const ull x0 = e[kk], x1 = e[k1];
                    const ull x0s = swp(x0), x1s = swp(x1);
                    e[kk] = f2(A,  x0, f2(Ai, x0s, f2(B, x1, m2(Bi,  x1s))));
                    e[k1] = f2(Bn, x0, f2(Bi, x0s, f2(A, x1, m2(Ain, x1s))));
                }
            }
        }

        #pragma unroll
        for (int kk = 0; kk < NE; kk++)
            psiu[syr ^ P.combo[kk]] = e[kk];
    }
}

// ================= kernel =================
extern __shared__ ull s_dyn[];   // [0,16384): psi ull ; then 16384 floats stage

__global__ void __launch_bounds__(NT, 1)
qsim_kernel(const float* __restrict__ state,
            const float* __restrict__ params,
            const float* __restrict__ head_w,
            const float* __restrict__ head_b,
            float* __restrict__ out)
{
    __shared__ ulonglong2 s_pkv[84 * 3];
    __shared__ float s_red[NT / 32][14];
    __shared__ float s_feat[14];
    ull*   psiu  = s_dyn;
    float* stage = (float*)(s_dyn + QDIM);

    const int tid = threadIdx.x;
    const int b0  = blockIdx.x;
    const int nelem = (QBATCH - b0 + NSM - 1) / NSM;

    // ---- gate coefficients once per CTA: U = RY(t2)*RX(t1) = [[a,b],[-b*,a*]] ----
    if (tid < 84) {
        const int g = tid >> 1, f = tid & 1;
        const float tx = params[g * 2 + 0] * 0.5f;
        const float ty = params[g * 2 + 1] * 0.5f;
        float s1, c1, s2, c2;
        sincosf(tx, &s1, &c1);
        sincosf(ty, &s2, &c2);
        float aR = c1 * c2, aI = s1 * s2;
        float bR = -s2 * c1, bI = -c2 * s1;
        if (f) { aI = -aI; bR = -bR; }
        ulonglong2* q = s_pkv + tid * 3;
        ulonglong2 t0, t1, t2;
        t0.x = pk2(aR, aR);   t0.y = pk2(-aI, aI);
        t1.x = pk2(aI, -aI);  t1.y = pk2(bR, bR);
        t2.x = pk2(-bR, -bR); t2.y = pk2(-bI, bI);
        q[0] = t0; q[1] = t1; q[2] = t2;
    }

    prefetch_state(stage, state + (size_t)b0 * QDIM, tid);

    constexpr unsigned MEAS[14] = {
        rowR(3, 0),  rowR(3, 1),  rowR(3, 2),  rowR(3, 3),
        rowR(3, 4),  rowR(3, 5),  rowR(3, 6),  rowR(3, 7),
        rowR(3, 8),  rowR(3, 9),  rowR(3, 10), rowR(3, 11),
        rowR(3, 12), rowR(3, 13)
    };

    for (int e = 0; e < nelem; e++) {
        const int b = b0 + e * NSM;

        asm volatile("cp.async.wait_group 0;" ::: "memory");
        __syncthreads();

        // pass 0 consumes stage (real input), writes psi
        do_pass<0, true >(psiu, stage, s_pkv, tid); __syncthreads();

        // stage free -> prefetch next element, overlapped with passes 1..11
        if (e + 1 < nelem)
            prefetch_state(stage, state + (size_t)(b + NSM) * QDIM, tid);

        do_pass<1,  false>(psiu, stage, s_pkv, tid); __syncthreads();
        do_pass<2,  false>(psiu, stage, s_pkv, tid); __syncthreads();
        do_pass<3,  false>(psiu, stage, s_pkv, tid); __syncthreads();
        do_pass<4,  false>(psiu, stage, s_pkv, tid); __syncthreads();
        do_pass<5,  false>(psiu, stage, s_pkv, tid); __syncthreads();
        do_pass<6,  false>(psiu, stage, s_pkv, tid); __syncthreads();
        do_pass<7,  false>(psiu, stage, s_pkv, tid); __syncthreads();
        do_pass<8,  false>(psiu, stage, s_pkv, tid); __syncthreads();
        do_pass<9,  false>(psiu, stage, s_pkv, tid); __syncthreads();
        do_pass<10, false>(psiu, stage, s_pkv, tid); __syncthreads();
        do_pass<11, false>(psiu, stage, s_pkv, tid); __syncthreads();

        // ---- measurement: probabilities + WHT over high 4 bits ----
        const float2* psf = (const float2*)psiu;
        float p[16];
        #pragma unroll
        for (int i = 0; i < 16; i++) {
            const unsigned y = (unsigned)tid + ((unsigned)i << 10);
            const float2 a = psf[sig(y)];
            p[i] = a.x * a.x + a.y * a.y;
        }
        #pragma unroll
        for (int s = 0; s < 4; s++) {
            #pragma unroll
            for (int kk = 0; kk < 16; kk++) {
                if (!((kk >> s) & 1)) {
                    const int k1 = kk | (1 << s);
                    const float u = p[kk], v = p[k1];
                    p[kk] = u + v;
                    p[k1] = u - v;
                }
            }
        }

        const int warp = tid >> 5, lane = tid & 31;
        #pragma unroll
        for (int w = 0; w < 14; w++) {
            const unsigned r = MEAS[w];
            float v = p[(r >> 10) & 15];
            v = (__popc(tid & r) & 1) ? -v : v;
            #pragma unroll
            for (int off = 16; off; off >>= 1)
                v += __shfl_xor_sync(0xffffffffu, v, off);
            if (lane == 0) s_red[warp][w] = v;
        }
        __syncthreads();

        if (tid < 14) {
            float f = 0.0f;
            #pragma unroll
            for (int q = 0; q < NT / 32; q++) f += s_red[q][tid];
            s_feat[tid] = f * head_w[tid];
        }
        __syncthreads();
        if (tid == 0) {
            float o = head_b[0];
            #pragma unroll
            for (int w = 0; w < 14; w++) o += s_feat[w];
            out[b] = o;
        }
    }
}

// ================= entry point =================
extern "C" void kernel_launch(void* const* d_in, const int* in_sizes, int n_in,
                              void* d_out, int out_size)
{
    (void)in_sizes; (void)n_in; (void)out_size;
    const float* state  = (const float*)d_in[0];
    const float* params = (const float*)d_in[1];
    const float* head_w = (const float*)d_in[2];
    const float* head_b = (const float*)d_in[3];
    float* out = (float*)d_out;

    const int smem = QDIM * (int)sizeof(ull) + QDIM * (int)sizeof(float); // 192 KB

    static bool attr_done = false;
    if (!attr_done) {
        cudaFuncSetAttribute(qsim_kernel,
                             cudaFuncAttributeMaxDynamicSharedMemorySize, smem);
        attr_done = true;
    }

    qsim_kernel<<<NSM, NT, smem>>>(state, params, head_w, head_b, out);
}

// round 8
// speedup vs baseline: 1.0782x; 1.0782x over previous
#include <cuda_runtime.h>
#include <math.h>

#define NW   14
#define QDIM 16384
#define QBATCH 1024
#define NT   1024

typedef unsigned long long ull;

// ================= compile-time GF(2) circuit algebra =================
__host__ __device__ constexpr unsigned sig(unsigned y) { return y ^ (y >> 7); }

struct PassC {
    unsigned combo[16];   // sigma-transformed XOR offsets (psi addressing)
    unsigned craw[16];    // raw XOR offsets (global addressing, pass 0)
    unsigned rmask[4];    // parity masks on logical rep yr
    int      gate[4];
    int      zflip[4];    // 1 if flip provably always 0
    int      K;
    int      ngrp;
    unsigned gmask[12];
    int      gshift[12];
};

__host__ __device__ constexpr unsigned hc(unsigned x, int c, int t) {
    int pc = 13 - c, pt = 13 - t;
    return x ^ (((x >> pc) & 1u) << pt);
}
__host__ __device__ constexpr unsigned Gf(unsigned x) {
    x = hc(x, 13, 0);
    for (int w = 12; w >= 0; --w) x = hc(x, w, w + 1);
    return x;
}
__host__ __device__ constexpr unsigned Gi(unsigned x) {
    for (int w = 0; w <= 12; ++w) x = hc(x, w, w + 1);
    x = hc(x, 13, 0);
    return x;
}
__host__ __device__ constexpr unsigned colV(int L, int w) {
    unsigned e = 1u << (13 - w);
    for (int i = 0; i < L; i++) e = Gf(e);
    return e;
}
__host__ __device__ constexpr unsigned rowR(int L, int w) {
    unsigned rr = 0;
    for (int j = 0; j < 14; j++) {
        unsigned e = 1u << j;
        for (int i = 0; i < L; i++) e = Gi(e);
        rr |= ((e >> (13 - w)) & 1u) << j;
    }
    return rr;
}

__host__ __device__ constexpr PassC build_pass(int pi) {
    PassC P = {};
    const int L = pi / 4, g = pi % 4;
    const int gstart[4] = {0, 4, 8, 11};
    const int gcnt[4]   = {4, 4, 3, 3};
    const int K = gcnt[g], base = gstart[g];

    unsigned vs[4] = {}, rs[4] = {};
    for (int j = 0; j < K; j++) {
        vs[j] = colV(L, base + j);
        rs[j] = rowR(L, base + j);
    }
    for (int kk = 0; kk < 16; kk++) {
        unsigned cb = 0;
        if (kk < (1 << K))
            for (int j = 0; j < K; j++)
                if ((kk >> j) & 1) cb ^= vs[j];
        P.craw[kk]  = cb;
        P.combo[kk] = sig(cb);
    }
    // Gaussian elimination, high-bit pivots
    bool ispiv[14] = {};
    unsigned red[4] = {}; int piv[4] = {};
    for (int j = 0; j < K; j++) {
        unsigned u = vs[j];
        for (int q = 0; q < j; q++)
            if ((u >> piv[q]) & 1u) u ^= red[q];
        int hb = 13;
        while (hb > 0 && !((u >> hb) & 1u)) hb--;
        piv[j] = hb; red[j] = u; ispiv[hb] = true;
    }
    const int NF = 14 - K;
    bool used[14] = {};
    for (int b = 0; b < 14; b++) used[b] = ispiv[b];

    // lane-bit placement: lane bit t -> position t or t+7 (bank-conflict-free sigma)
    int Pm[14] = {};
    for (int t = 0; t < 4; t++) {
        int pos = -1;
        if (!used[t]) pos = t;
        else if (!used[t + 7]) pos = t + 7;
        if (pos >= 0) { used[pos] = true; Pm[t] = pos; }
        else Pm[t] = -1;
    }
    for (int t = 0; t < 4; t++) {
        if (Pm[t] < 0) {
            for (int b = 0; b < 14; b++)
                if (!used[b]) { Pm[t] = b; used[b] = true; break; }
        }
    }
    int idx = 4;
    for (int b = 0; b < 14; b++)
        if (!used[b]) { Pm[idx++] = b; used[b] = true; }

    unsigned freemask = 0;
    for (int i = 0; i < NF; i++) freemask |= 1u << Pm[i];

    for (int j = 0; j < 4; j++) {
        P.rmask[j] = (j < K) ? rs[j] : 0u;
        P.gate[j]  = (j < K) ? (L * 14 + base + j) : 0;
        P.zflip[j] = (j < K) ? (((rs[j] & freemask) == 0u) ? 1 : 0) : 1;
    }

    // run-compress (o bit i -> position Pm[i]) into (mask, shift) groups
    P.K = K; P.ngrp = 0;
    int i = 0;
    while (i < NF) {
        int d = Pm[i] - i;
        unsigned m = 0; int j2 = i;
        while (j2 < NF && Pm[j2] - j2 == d) { m |= 1u << j2; j2++; }
        P.gmask[P.ngrp]  = m;
        P.gshift[P.ngrp] = d;
        P.ngrp++;
        i = j2;
    }
    return P;
}

// ================= packed f32x2 helpers =================
__device__ __forceinline__ ull pk2(float lo, float hi) {
    ull r;
    asm("mov.b64 %0, {%1, %2};" : "=l"(r) : "f"(lo), "f"(hi));
    return r;
}
__device__ __forceinline__ ull swp(ull v) {
    unsigned lo, hi;
    asm("mov.b64 {%0, %1}, %2;" : "=r"(lo), "=r"(hi) : "l"(v));
    ull r;
    asm("mov.b64 %0, {%1, %2};" : "=l"(r) : "r"(hi), "r"(lo));
    return r;
}
__device__ __forceinline__ ull f2(ull a, ull b, ull c) {
    ull d;
    asm("fma.rn.f32x2 %0, %1, %2, %3;" : "=l"(d) : "l"(a), "l"(b), "l"(c));
    return d;
}
__device__ __forceinline__ ull m2(ull a, ull b) {
    ull d;
    asm("mul.rn.f32x2 %0, %1, %2;" : "=l"(d) : "l"(a), "l"(b));
    return d;
}

// ================= fused-gate pass =================
// FIRST=true: read real amplitudes directly from global (coalesced), im = 0.
template<int PI, bool FIRST>
__device__ __forceinline__ void do_pass(ull* psiu, const float* __restrict__ gsrc,
                                        const ulonglong2* pkv, int tid)
{
    constexpr PassC P  = build_pass(PI);
    constexpr int K    = P.K;
    constexpr int NE   = 1 << K;
    constexpr int NORB = 1 << (NW - K);

    #pragma unroll
    for (int o = tid; o < NORB; o += NT) {
        unsigned yr = 0;
        #pragma unroll
        for (int g = 0; g < P.ngrp; g++)
            yr |= ((unsigned)o & P.gmask[g]) << P.gshift[g];
        const unsigned syr = sig(yr);

        ull e[NE];
        if (FIRST) {
            #pragma unroll
            for (int kk = 0; kk < NE; kk++)
                e[kk] = pk2(__ldg(gsrc + (yr ^ P.craw[kk])), 0.0f);
        } else {
            #pragma unroll
            for (int kk = 0; kk < NE; kk++)
                e[kk] = psiu[syr ^ P.combo[kk]];
        }

        #pragma unroll
        for (int j = 0; j < K; j++) {
            const int flip = P.zflip[j] ? 0 : (__popc(yr & P.rmask[j]) & 1);
            const ulonglong2* cp = pkv + (size_t)((P.gate[j] << 1) + flip) * 3;
            const ulonglong2 c0 = cp[0], c1 = cp[1], c2 = cp[2];
            const ull A = c0.x, Ai = c0.y, Ain = c1.x;
            const ull B = c1.y, Bn = c2.x, Bi  = c2.y;
            #pragma unroll
            for (int kk = 0; kk < NE; kk++) {
                if (!((kk >> j) & 1)) {
                    const int k1 = kk | (1 << j);
                    const ull x0 = e[kk], x1 = e[k1];
                    const ull x0s = swp(x0), x1s = swp(x1);
                    e[kk] = f2(A,  x0, f2(Ai, x0s, f2(B, x1, m2(Bi,  x1s))));
                    e[k1] = f2(Bn, x0, f2(Bi, x0s, f2(A, x1, m2(Ain, x1s))));
                }
            }
        }

        #pragma unroll
        for (int kk = 0; kk < NE; kk++)
            psiu[syr ^ P.combo[kk]] = e[kk];
    }
}

// ================= kernel =================
extern __shared__ ull s_psi[];   // 16384 packed (re,im) amplitudes, sigma layout

__global__ void __launch_bounds__(NT, 1)
qsim_kernel(const float* __restrict__ state,
            const float* __restrict__ params,
            const float* __restrict__ head_w,
            const float* __restrict__ head_b,
            float* __restrict__ out)
{
    __shared__ ulonglong2 s_pkv[84 * 3];
    __shared__ float s_red[NT / 32][14];
    __shared__ float s_feat[14];
    ull* psiu = s_psi;

    const int tid = threadIdx.x;
    const int b   = blockIdx.x;
    const float* gsrc = state + (size_t)b * QDIM;

    // ---- gate coefficients: U = RY(t2)*RX(t1) = [[a,b],[-b*,a*]] ----
    if (tid < 84) {
        const int g = tid >> 1, f = tid & 1;
        const float tx = params[g * 2 + 0] * 0.5f;
        const float ty = params[g * 2 + 1] * 0.5f;
        float s1, c1, s2, c2;
        sincosf(tx, &s1, &c1);
        sincosf(ty, &s2, &c2);
        float aR = c1 * c2, aI = s1 * s2;
        float bR = -s2 * c1, bI = -c2 * s1;
        if (f) { aI = -aI; bR = -bR; }
        ulonglong2* q = s_pkv + tid * 3;
        ulonglong2 t0, t1, t2;
        t0.x = pk2(aR, aR);   t0.y = pk2(-aI, aI);
        t1.x = pk2(aI, -aI);  t1.y = pk2(bR, bR);
        t2.x = pk2(-bR, -bR); t2.y = pk2(-bI, bI);
        q[0] = t0; q[1] = t1; q[2] = t2;
    }
    __syncthreads();

    // ---- 12 fused-gate passes; pass 0 reads global directly ----
    do_pass<0,  true >(psiu, gsrc, s_pkv, tid); __syncthreads();
    do_pass<1,  false>(psiu, gsrc, s_pkv, tid); __syncthreads();
    do_pass<2,  false>(psiu, gsrc, s_pkv, tid); __syncthreads();
    do_pass<3,  false>(psiu, gsrc, s_pkv, tid); __syncthreads();
    do_pass<4,  false>(psiu, gsrc, s_pkv, tid); __syncthreads();
    do_pass<5,  false>(psiu, gsrc, s_pkv, tid); __syncthreads();
    do_pass<6,  false>(psiu, gsrc, s_pkv, tid); __syncthreads();
    do_pass<7,  false>(psiu, gsrc, s_pkv, tid); __syncthreads();
    do_pass<8,  false>(psiu, gsrc, s_pkv, tid); __syncthreads();
    do_pass<9,  false>(psiu, gsrc, s_pkv, tid); __syncthreads();
    do_pass<10, false>(psiu, gsrc, s_pkv, tid); __syncthreads();
    do_pass<11, false>(psiu, gsrc, s_pkv, tid); __syncthreads();

    // ---- measurement: probabilities + WHT over high 4 bits ----
    const float2* psf = (const float2*)psiu;
    float p[16];
    #pragma unroll
    for (int i = 0; i < 16; i++) {
        const unsigned y = (unsigned)tid + ((unsigned)i << 10);
        const float2 a = psf[sig(y)];
        p[i] = a.x * a.x + a.y * a.y;
    }
    #pragma unroll
    for (int s = 0; s < 4; s++) {
        #pragma unroll
        for (int kk = 0; kk < 16; kk++) {
            if (!((kk >> s) & 1)) {
                const int k1 = kk | (1 << s);
                const float u = p[kk], v = p[k1];
                p[kk] = u + v;
                p[k1] = u - v;
            }
        }
    }

    constexpr unsigned MEAS[14] = {
        rowR(3, 0),  rowR(3, 1),  rowR(3, 2),  rowR(3, 3),
        rowR(3, 4),  rowR(3, 5),  rowR(3, 6),  rowR(3, 7),
        rowR(3, 8),  rowR(3, 9),  rowR(3, 10), rowR(3, 11),
        rowR(3, 12), rowR(3, 13)
    };

    const int warp = tid >> 5, lane = tid & 31;
    #pragma unroll
    for (int w = 0; w < 14; w++) {
        const unsigned r = MEAS[w];
        float v = p[(r >> 10) & 15];
        v = (__popc(tid & r) & 1) ? -v : v;
        #pragma unroll
        for (int off = 16; off; off >>= 1)
            v += __shfl_xor_sync(0xffffffffu, v, off);
        if (lane == 0) s_red[warp][w] = v;
    }
    __syncthreads();

    if (tid < 14) {
        float f = 0.0f;
        #pragma unroll
        for (int q = 0; q < NT / 32; q++) f += s_red[q][tid];
        s_feat[tid] = f * head_w[tid];
    }
    __syncthreads();
    if (tid == 0) {
        float o = head_b[0];
        #pragma unroll
        for (int w = 0; w < 14; w++) o += s_feat[w];
        out[b] = o;
    }
}

// ================= entry point =================
extern "C" void kernel_launch(void* const* d_in, const int* in_sizes, int n_in,
                              void* d_out, int out_size)
{
    (void)in_sizes; (void)n_in; (void)out_size;
    const float* state  = (const float*)d_in[0];
    const float* params = (const float*)d_in[1];
    const float* head_w = (const float*)d_in[2];
    const float* head_b = (const float*)d_in[3];
    float* out = (float*)d_out;

    const int smem = QDIM * (int)sizeof(ull);   // 128 KB

    static bool attr_done = false;
    if (!attr_done) {
        cudaFuncSetAttribute(qsim_kernel,
                             cudaFuncAttributeMaxDynamicSharedMemorySize, smem);
        attr_done = true;
    }

    qsim_kernel<<<QBATCH, NT, smem>>>(state, params, head_w, head_b, out);
}